// round 3
// baseline (speedup 1.0000x reference)
#include <cuda_runtime.h>

// context[b,d] = sum_t keys[b,t,d]   (softmax over size-1 axis == 1; rest dead)
// R3: contiguous-streaming blocks (HBM row-buffer locality) + perfect wave
// balance (608 blocks = 2 full waves on 152 SMs @ occ 2). Two-pass reduction
// through a static __device__ partial buffer (no allocations, deterministic).

#define B_SZ   32
#define D4     128          // 512 floats = 128 float4 per row
#define NSLAB  19           // 32*19 = 608 blocks = 2 * (152 SMs * 2 blocks)
#define NGRP   512          // 4096 rows / 8 rows-per-iteration
#define GPS    27           // groups per slab (last slab gets 512-18*27 = 26)

__device__ float4 g_partial[B_SZ * NSLAB * D4];   // 1.2 MB scratch

// Block = (b, slab). 1024 threads read 8 rows (16 KB) per iteration, fully
// contiguous. Thread's float4-column = tid & 127 is invariant across iters.
__global__ __launch_bounds__(1024, 2)
void sum_slab_kernel(const float4* __restrict__ keys4) {
    const int bid = blockIdx.x;            // 0..607
    const int b   = bid / NSLAB;
    const int s   = bid - b * NSLAB;
    const int g0  = s * GPS;
    const int ng  = (s == NSLAB - 1) ? (NGRP - g0) : GPS;   // 27 or 26
    const int tid = threadIdx.x;

    // batch slab base: b * 4096 rows * 128 f4 + g0 * (8 rows * 128 f4)
    const float4* p = keys4 + b * (4096 * D4) + g0 * 1024 + tid;

    float4 acc = make_float4(0.f, 0.f, 0.f, 0.f);
    #pragma unroll 4
    for (int i = 0; i < ng; ++i) {
        float4 v = __ldcs(p + i * 1024);
        acc.x += v.x; acc.y += v.y; acc.z += v.z; acc.w += v.w;
    }

    // reduce the 8 row-phases (tid>>7) per column (tid&127)
    __shared__ float4 sm[1024];
    sm[tid] = acc;
    __syncthreads();
    if (tid < 512) {
        float4 o = sm[tid + 512];
        sm[tid].x += o.x; sm[tid].y += o.y; sm[tid].z += o.z; sm[tid].w += o.w;
    }
    __syncthreads();
    if (tid < 256) {
        float4 o = sm[tid + 256];
        sm[tid].x += o.x; sm[tid].y += o.y; sm[tid].z += o.z; sm[tid].w += o.w;
    }
    __syncthreads();
    if (tid < 128) {
        float4 m = sm[tid];
        float4 o = sm[tid + 128];
        m.x += o.x; m.y += o.y; m.z += o.z; m.w += o.w;
        g_partial[(b * NSLAB + s) * D4 + tid] = m;
    }
}

// Sum the NSLAB partials per output column. 4096 float4 outputs.
__global__ void finalize_kernel(float4* __restrict__ out4) {
    const int gid = blockIdx.x * 256 + threadIdx.x;   // 0..4095
    const int b = gid >> 7;
    const int c = gid & 127;
    float4 acc = make_float4(0.f, 0.f, 0.f, 0.f);
    #pragma unroll
    for (int s = 0; s < NSLAB; ++s) {
        float4 v = g_partial[(b * NSLAB + s) * D4 + c];
        acc.x += v.x; acc.y += v.y; acc.z += v.z; acc.w += v.w;
    }
    out4[gid] = acc;
}

extern "C" void kernel_launch(void* const* d_in, const int* in_sizes, int n_in,
                              void* d_out, int out_size) {
    // metadata order: query[0], keys[1], Ws[2], Wh[3], W[4]; only keys is live.
    const float4* keys4 = (const float4*)d_in[1];
    float4* out4 = (float4*)d_out;

    sum_slab_kernel<<<B_SZ * NSLAB, 1024>>>(keys4);
    finalize_kernel<<<16, 256>>>(out4);
}